// round 11
// baseline (speedup 1.0000x reference)
#include <cuda_runtime.h>
#include <cstdint>

#define W 8192
#define H 2048
#define NPIX (W * H)
#define THREADS 256
#define PX_PER_BLOCK 2048
#define CHUNKS (PX_PER_BLOCK / THREADS)          // 8
#define NBLOCKS (NPIX / PX_PER_BLOCK)            // 8192
#define IMG_BYTES_PER_BLOCK (PX_PER_BLOCK * 16)  // 32768
#define OUT_BYTES_HALF (PX_PER_BLOCK * 6)        // 12288 per half

#define FOV_SPAN     0.5235987755982988f
#define FOV_ABS_DOWN 0.2617993877991494f
#define TWO_PI       6.283185307179586f
#define PI_F         3.141592653589793f

// Rotation by 256 column steps: delta = 256 * 2*pi/8192 = pi/16
#define ROT_C 0.9807852804032304f
#define ROT_S 0.1950903220161283f

__device__ __forceinline__ uint32_t smem_u32(const void* p) {
    uint32_t a;
    asm("{ .reg .u64 t; cvta.to.shared.u64 t, %1; cvt.u32.u64 %0, t; }"
        : "=r"(a) : "l"(p));
    return a;
}

// R8/R9 structure, store path reworked:
//  - store split into two 12 KB TMA ops; the first departs while the second
//    half is still being computed (overlap write drain with compute)
//  - block exits only after cp.async.bulk.wait_group 0 (FULL completion, not
//    .read): writes reach global visibility inside the block's lifetime,
//    hidden by the other resident blocks, instead of piling into an
//    end-of-grid drain that ncu doesn't see but wallclock pays (the
//    invariant ~7.5us total-kernel gap since TMA stores landed in R6).
__global__ void __launch_bounds__(THREADS)
proj_to_pointcloud_kernel(const float* __restrict__ img, float* __restrict__ out) {
    __shared__ alignas(128) float s_buf[PX_PER_BLOCK * 4];   // 32 KB, dual-use
    __shared__ alignas(8)   uint64_t s_mbar;

    int t = threadIdx.x;
    long blockBase = (long)blockIdx.x * PX_PER_BLOCK;
    int row = (int)(blockBase >> 13);
    int j0  = (int)(blockBase & (W - 1));
    uint32_t mb = smem_u32(&s_mbar);

    if (t == 0) {
        asm volatile("mbarrier.init.shared.b64 [%0], %1;" :: "r"(mb), "r"(1));
    }
    __syncthreads();

    if (t == 0) {
        asm volatile("mbarrier.arrive.expect_tx.shared.b64 _, [%0], %1;"
                     :: "r"(mb), "r"(IMG_BYTES_PER_BLOCK) : "memory");
        uint32_t dstp = smem_u32(s_buf);
        const float* srcp = img + (blockBase << 2);
        asm volatile(
            "cp.async.bulk.shared::cta.global.mbarrier::complete_tx::bytes "
            "[%0], [%1], %2, [%3];"
            :: "r"(dstp), "l"(srcp), "n"(IMG_BYTES_PER_BLOCK), "r"(mb) : "memory");
    }

    // ---- trig, overlapped with the TMA load ----
    float yaw = (float)(j0 + t) * (TWO_PI / (float)W) - PI_F;
    float s, c;
    sincosf(yaw, &s, &c);
    float pitch = (1.0f - (float)row / (float)H) * FOV_SPAN - FOV_ABS_DOWN;
    float sp = sinf(pitch);

    // ---- wait for image tile ----
    asm volatile(
        "{\n\t"
        ".reg .pred P;\n\t"
        "WAIT_%=:\n\t"
        "mbarrier.try_wait.parity.acquire.cta.shared::cta.b64 P, [%0], %1, 0x989680;\n\t"
        "@P bra DONE_%=;\n\t"
        "bra WAIT_%=;\n\t"
        "DONE_%=:\n\t"
        "}" :: "r"(mb), "r"(0) : "memory");

    // ---- extract all depths to registers (buffer gets overwritten) ----
    float d[CHUNKS];
    #pragma unroll
    for (int i = 0; i < CHUNKS; i++) {
        d[i] = s_buf[4 * (i * THREADS + t) + 3];
    }
    __syncthreads();   // all reads done before any xyz overwrite

    // ---- first half: pixels 0..1023 -> s_buf[0..3071] ----
    #pragma unroll
    for (int i = 0; i < CHUNKS / 2; i++) {
        int p = i * THREADS + t;
        s_buf[3 * p + 0] =  d[i] * c;
        s_buf[3 * p + 1] = -d[i] * s;
        s_buf[3 * p + 2] =  d[i] * sp;
        float cn = fmaf(c, ROT_C, -s * ROT_S);
        float sn = fmaf(s, ROT_C,  c * ROT_S);
        c = cn; s = sn;
    }
    __syncthreads();

    if (t == 0) {
        asm volatile("fence.proxy.async.shared::cta;" ::: "memory");
        asm volatile(
            "cp.async.bulk.global.shared::cta.bulk_group [%0], [%1], %2;"
            :: "l"(out + blockBase * 3), "r"(smem_u32(s_buf)), "n"(OUT_BYTES_HALF)
            : "memory");
        asm volatile("cp.async.bulk.commit_group;" ::: "memory");
    }

    // ---- second half: pixels 1024..2047 -> s_buf[3072..6143] ----
    #pragma unroll
    for (int i = CHUNKS / 2; i < CHUNKS; i++) {
        int p = i * THREADS + t;
        s_buf[3 * p + 0] =  d[i] * c;
        s_buf[3 * p + 1] = -d[i] * s;
        s_buf[3 * p + 2] =  d[i] * sp;
        float cn = fmaf(c, ROT_C, -s * ROT_S);
        float sn = fmaf(s, ROT_C,  c * ROT_S);
        c = cn; s = sn;
    }
    __syncthreads();

    if (t == 0) {
        asm volatile("fence.proxy.async.shared::cta;" ::: "memory");
        asm volatile(
            "cp.async.bulk.global.shared::cta.bulk_group [%0], [%1], %2;"
            :: "l"(out + blockBase * 3 + PX_PER_BLOCK / 2 * 3),
               "r"(smem_u32(s_buf) + (uint32_t)OUT_BYTES_HALF), "n"(OUT_BYTES_HALF)
            : "memory");
        asm volatile("cp.async.bulk.commit_group;" ::: "memory");
        // FULL completion: writes globally visible before block exit.
        asm volatile("cp.async.bulk.wait_group 0;" ::: "memory");
    }
}

extern "C" void kernel_launch(void* const* d_in, const int* in_sizes, int n_in,
                              void* d_out, int out_size) {
    const float* img = (const float*)d_in[0];
    float* out = (float*)d_out;
    proj_to_pointcloud_kernel<<<NBLOCKS, THREADS>>>(img, out);
}